// round 16
// baseline (speedup 1.0000x reference)
#include <cuda_runtime.h>
#include <cuda_fp16.h>
#include <math_constants.h>

#define N_NODES 50000
#define N_EDGES 800000
#define DIM 64
#define NCHUNK 98          // 98*512 = 50176 >= 50000 ; co-resident for lookback scan
#define NCONV (N_NODES * DIM / 8)   // 400000 conv work-items (8 floats each)
#define XS_STRIDE 72       // halves; 144B rows -> ldmatrix conflict-free

// ---- device scratch (no allocations allowed; static zero-init) ----
__device__ int   g_counts[N_NODES];      // invariant: zero at entry of every replay
__device__ int   g_offsets[N_NODES + 1];
__device__ int   g_cursor[N_NODES];
__device__ int   g_csum[NCHUNK];
__device__ volatile int g_cflag[NCHUNK]; // invariant: zero at entry (reset by k_scatter)
__device__ int   g_srcidx[N_EDGES];
__device__ float g_h0[N_NODES * DIM];
__device__ float g_h1[N_NODES * DIM];
__device__ __align__(16) __half g_hha[N_NODES * DIM];  // fp16 shadow (ping)
__device__ __align__(16) __half g_hhb[N_NODES * DIM];  // fp16 shadow (pong)

// ---- mma helpers ----
__device__ __forceinline__ void ldsm_x4(unsigned* r, unsigned addr) {
    asm volatile("ldmatrix.sync.aligned.m8n8.x4.shared.b16 {%0,%1,%2,%3}, [%4];"
        : "=r"(r[0]), "=r"(r[1]), "=r"(r[2]), "=r"(r[3]) : "r"(addr));
}
__device__ __forceinline__ void ldsm_x4_t(unsigned* r, unsigned addr) {
    asm volatile("ldmatrix.sync.aligned.m8n8.x4.trans.shared.b16 {%0,%1,%2,%3}, [%4];"
        : "=r"(r[0]), "=r"(r[1]), "=r"(r[2]), "=r"(r[3]) : "r"(addr));
}
__device__ __forceinline__ void mma16816(float* d, const unsigned* a,
                                         unsigned b0, unsigned b1) {
    asm volatile(
        "mma.sync.aligned.m16n8k16.row.col.f32.f16.f16.f32 "
        "{%0,%1,%2,%3}, {%4,%5,%6,%7}, {%8,%9}, {%0,%1,%2,%3};"
        : "+f"(d[0]), "+f"(d[1]), "+f"(d[2]), "+f"(d[3])
        : "r"(a[0]), "r"(a[1]), "r"(a[2]), "r"(a[3]), "r"(b0), "r"(b1));
}

// ---- gather batch helpers (max is idempotent: overlapping re-reads are safe) ----
__device__ __forceinline__ __half2 gmax16(const __half* __restrict__ hh,
                                          int i, int lane, __half2 m) {
    int sx[16];
    #pragma unroll
    for (int u = 0; u < 16; u++) sx[u] = __ldg(&g_srcidx[i + u]);
    __half2 a[16];
    #pragma unroll
    for (int u = 0; u < 16; u++)
        a[u] = __ldg((const __half2*)(hh + (size_t)sx[u] * DIM) + lane);
    #pragma unroll
    for (int u = 0; u < 16; u++) m = __hmax2(m, a[u]);
    return m;
}
__device__ __forceinline__ __half2 gmax8(const __half* __restrict__ hh,
                                         int i, int lane, __half2 m) {
    int sx[8];
    #pragma unroll
    for (int u = 0; u < 8; u++) sx[u] = __ldg(&g_srcidx[i + u]);
    __half2 a[8];
    #pragma unroll
    for (int u = 0; u < 8; u++)
        a[u] = __ldg((const __half2*)(hh + (size_t)sx[u] * DIM) + lane);
    #pragma unroll
    for (int u = 0; u < 8; u++) m = __hmax2(m, a[u]);
    return m;
}

// ---------------- CSR build ----------------

// fused: degree count (1 edge/thread, max TLP) + fp16 conversion of n_feat
__global__ void k_count_conv(const int* __restrict__ dst,
                             const float* __restrict__ f) {
    int i = blockIdx.x * blockDim.x + threadIdx.x;
    if (i < N_EDGES)
        atomicAdd(&g_counts[__ldg(dst + i)], 1);
    if (i < NCONV) {
        float4 v0 = __ldg((const float4*)f + i * 2);
        float4 v1 = __ldg((const float4*)f + i * 2 + 1);
        __half2 hs[4];
        hs[0] = __floats2half2_rn(v0.x, v0.y);
        hs[1] = __floats2half2_rn(v0.z, v0.w);
        hs[2] = __floats2half2_rn(v1.x, v1.y);
        hs[3] = __floats2half2_rn(v1.z, v1.w);
        *(uint4*)((__half2*)g_hha + i * 4) = *(uint4*)hs;
    }
}

// single-kernel scan via decoupled lookback (all 98 blocks co-resident)
__global__ void __launch_bounds__(512) k_scan() {
    __shared__ int warp_sums[16];
    __shared__ int prefix_s;
    const int t = threadIdx.x, lane = t & 31, wid = t >> 5;
    const int c = blockIdx.x;
    const int i = c * 512 + t;

    int v = (i < N_NODES) ? g_counts[i] : 0;
    int s = v;
    #pragma unroll
    for (int d = 1; d < 32; d <<= 1) {
        int y = __shfl_up_sync(0xffffffffu, s, d);
        if (lane >= d) s += y;
    }
    if (lane == 31) warp_sums[wid] = s;
    __syncthreads();
    if (wid == 0 && lane < 16) {
        int ws = warp_sums[lane];
        #pragma unroll
        for (int d = 1; d < 16; d <<= 1) {
            int y = __shfl_up_sync(0xffffu, ws, d);
            if (lane >= d) ws += y;
        }
        warp_sums[lane] = ws;
    }
    __syncthreads();
    int excl = s - v + (wid > 0 ? warp_sums[wid - 1] : 0);

    if (t == 511) {
        g_csum[c] = excl + v;
        __threadfence();
        g_cflag[c] = 1;
    }
    if (t < 32) {
        int acc = 0;
        for (int j = lane; j < c; j += 32) {
            while (g_cflag[j] == 0) { }
            acc += *(volatile int*)&g_csum[j];
        }
        #pragma unroll
        for (int d = 16; d > 0; d >>= 1) acc += __shfl_down_sync(0xffffffffu, acc, d);
        if (lane == 0) prefix_s = acc;
    }
    __syncthreads();
    int prefix = prefix_s;

    if (i < N_NODES) {
        int o = excl + prefix;
        g_offsets[i] = o;
        g_cursor[i]  = o;
        g_counts[i]  = 0;
    }
    if (c == NCHUNK - 1 && t == 511)
        g_offsets[N_NODES] = prefix + excl + v;
}

// 2 edges per thread (int2), 400K threads for latency hiding
__global__ void k_scatter(const int* __restrict__ src, const int* __restrict__ dst) {
    int i = blockIdx.x * blockDim.x + threadIdx.x;
    if (i < NCHUNK) g_cflag[i] = 0;              // flag reset (invariant)
    if (i < N_EDGES / 2) {
        int2 s2 = __ldg((const int2*)src + i);
        int2 d2 = __ldg((const int2*)dst + i);
        g_srcidx[atomicAdd(&g_cursor[d2.x], 1)] = s2.x;
        g_srcidx[atomicAdd(&g_cursor[d2.y], 1)] = s2.y;
    }
}

// ---------------- fused layer: agg (fp16 segment-max) + mma.sync GEMM ----------
// 512 threads, tile = 64 nodes.
// Agg: warp per node (4 nodes/warp), half2 gathers, batch-16 with
//      OVERLAPPED TAIL batches (max idempotent -> re-reads free, no scalar drain
//      except deg<8 nodes, ~1% under Poisson(16)).
// GEMM: 16 warps x (m16 x n16) output tiles, mma.sync.m16n8k16 f16->f32.
__global__ void __launch_bounds__(512, 3) k_layer(
        const float* __restrict__ h,          // fp32 h (self term)
        const __half* __restrict__ hh,        // fp16 shadow of h (gathers)
        const float* __restrict__ W,
        const float* __restrict__ bias,
        const float* __restrict__ eps, int layer,
        float* __restrict__ out,
        __half* __restrict__ hh_out,          // fp16 shadow of out (or unused)
        int activate, int write_hh) {
    __shared__ __half Wsh[64 * XS_STRIDE];    // [k][j] fp16
    __shared__ __half Xsh[64 * XS_STRIDE];    // [node][k] fp16

    int t = threadIdx.x;              // 0..511
    int base = blockIdx.x * 64;

    // convert W to fp16 smem (each thread: 2 float4 = 8 values)
    #pragma unroll
    for (int p = 0; p < 2; p++) {
        int i4 = t + p * 512;         // 0..1023 float4s
        float4 w = __ldg((const float4*)W + i4);
        int kk = i4 >> 4;             // 16 float4 per 64-col row
        int j  = (i4 & 15) * 4;
        __half2* d2 = (__half2*)&Wsh[kk * XS_STRIDE + j];
        d2[0] = __floats2half2_rn(w.x, w.y);
        d2[1] = __floats2half2_rn(w.z, w.w);
    }

    float ep = 1.0f + __ldg(eps + layer);
    int warp = t >> 5, lane = t & 31;

    // ---- phase 1: fp16 aggregation, overlapped batch-16/8 tails ----
    #pragma unroll
    for (int q = 0; q < 4; q++) {
        int nl = warp * 4 + q;
        int n = base + nl;
        if (n < N_NODES) {
            int beg = g_offsets[n];
            int end = g_offsets[n + 1];
            int deg = end - beg;
            __half2 m = __float2half2_rn(-CUDART_INF_F);
            if (deg >= 16) {
                int i = beg;
                for (; i + 16 <= end; i += 16) m = gmax16(hh, i, lane, m);
                if (i < end) m = gmax16(hh, end - 16, lane, m);  // overlap re-read
            } else if (deg >= 8) {
                m = gmax8(hh, beg, lane, m);
                if (deg > 8) m = gmax8(hh, end - 8, lane, m);    // overlap re-read
            } else {
                for (int i = beg; i < end; ++i) {
                    int s = __ldg(&g_srcidx[i]);
                    __half2 a = __ldg((const __half2*)(hh + (size_t)s * DIM) + lane);
                    m = __hmax2(m, a);
                }
            }
            float2 mf = __half22float2(m);
            if (deg == 0) { mf.x = 0.0f; mf.y = 0.0f; }   // DGL zero-fill
            float2 hs = __ldg((const float2*)(h + (size_t)n * DIM) + lane);
            float xx = fmaf(ep, hs.x, mf.x);
            float xy = fmaf(ep, hs.y, mf.y);
            *(__half2*)&Xsh[nl * XS_STRIDE + lane * 2] = __floats2half2_rn(xx, xy);
        }
    }
    __syncthreads();                  // Wsh + Xsh ready

    // ---- phase 2: tensor-core GEMM out[64x64] = Xsh @ Wsh ----
    int warpM = warp >> 2;            // 0..3 : node rows warpM*16..+15
    int warpN = warp & 3;             // 0..3 : cols warpN*16..+15
    int lr = lane & 15, lc = lane >> 4;

    unsigned xs_u32 = (unsigned)__cvta_generic_to_shared(Xsh);
    unsigned ws_u32 = (unsigned)__cvta_generic_to_shared(Wsh);

    unsigned a_addr = xs_u32 + (((warpM * 16 + lr) * XS_STRIDE) + lc * 8) * 2;
    unsigned b_addr = ws_u32 + ((lr * XS_STRIDE) + warpN * 16 + lc * 8) * 2;

    float acc0[4] = {0.f, 0.f, 0.f, 0.f};
    float acc1[4] = {0.f, 0.f, 0.f, 0.f};

    #pragma unroll
    for (int kk = 0; kk < 4; kk++) {
        unsigned a[4], b[4];
        ldsm_x4(a, a_addr + kk * 32);                         // +16 halves
        ldsm_x4_t(b, b_addr + kk * 16 * XS_STRIDE * 2);       // +16 k-rows
        mma16816(acc0, a, b[0], b[1]);
        mma16816(acc1, a, b[2], b[3]);
    }

    // ---- epilogue: bias + leaky + store fp32 out (+ fp16 shadow) ----
    int r  = lane >> 2;               // row within m16 (and +8)
    int cq = lane & 3;                // col quad
    int n0 = base + warpM * 16 + r;
    int n1 = n0 + 8;

    #pragma unroll
    for (int nn = 0; nn < 2; nn++) {
        float* acc = nn ? acc1 : acc0;
        int col = warpN * 16 + nn * 8 + cq * 2;
        float2 bb = *(const float2*)(bias + col);
        float v0 = acc[0] + bb.x, v1 = acc[1] + bb.y;   // row r
        float v2 = acc[2] + bb.x, v3 = acc[3] + bb.y;   // row r+8
        if (activate) {
            v0 = v0 >= 0.f ? v0 : 0.01f * v0;
            v1 = v1 >= 0.f ? v1 : 0.01f * v1;
            v2 = v2 >= 0.f ? v2 : 0.01f * v2;
            v3 = v3 >= 0.f ? v3 : 0.01f * v3;
        }
        if (n0 < N_NODES) {
            *(float2*)&out[(size_t)n0 * DIM + col] = make_float2(v0, v1);
            if (write_hh)
                *(__half2*)(hh_out + (size_t)n0 * DIM + col) = __floats2half2_rn(v0, v1);
        }
        if (n1 < N_NODES) {
            *(float2*)&out[(size_t)n1 * DIM + col] = make_float2(v2, v3);
            if (write_hh)
                *(__half2*)(hh_out + (size_t)n1 * DIM + col) = __floats2half2_rn(v2, v3);
        }
    }
}

// ---------------- launch ----------------
extern "C" void kernel_launch(void* const* d_in, const int* in_sizes, int n_in,
                              void* d_out, int out_size) {
    const float* n_feat = (const float*)d_in[0];
    const float* W0 = (const float*)d_in[1];
    const float* b0 = (const float*)d_in[2];
    const float* W1 = (const float*)d_in[3];
    const float* b1 = (const float*)d_in[4];
    const float* W2 = (const float*)d_in[5];
    const float* b2 = (const float*)d_in[6];
    const float* eps = (const float*)d_in[7];
    const int*   src = (const int*)d_in[8];
    const int*   dst = (const int*)d_in[9];
    float* out = (float*)d_out;

    float *h0_ptr, *h1_ptr;
    __half *hha_ptr, *hhb_ptr;
    cudaGetSymbolAddress((void**)&h0_ptr, g_h0);
    cudaGetSymbolAddress((void**)&h1_ptr, g_h1);
    cudaGetSymbolAddress((void**)&hha_ptr, g_hha);
    cudaGetSymbolAddress((void**)&hhb_ptr, g_hhb);

    // CSR build + fp16 conversion (3 launches)
    k_count_conv<<<(N_EDGES + 255) / 256, 256>>>(dst, n_feat);
    k_scan<<<NCHUNK, 512>>>();
    k_scatter<<<(N_EDGES / 2 + 255) / 256, 256>>>(src, dst);

    const int layer_blocks = (N_NODES + 63) / 64;   // 782

    k_layer<<<layer_blocks, 512>>>(n_feat, hha_ptr, W0, b0, eps, 0,
                                   h0_ptr, hhb_ptr, 1, 1);
    k_layer<<<layer_blocks, 512>>>(h0_ptr, hhb_ptr, W1, b1, eps, 1,
                                   h1_ptr, hha_ptr, 1, 1);
    k_layer<<<layer_blocks, 512>>>(h1_ptr, hha_ptr, W2, b2, eps, 2,
                                   out, hhb_ptr, 0, 0);
}

// round 17
// speedup vs baseline: 1.0735x; 1.0735x over previous
#include <cuda_runtime.h>
#include <cuda_fp16.h>
#include <math_constants.h>

#define N_NODES 50000
#define N_EDGES 800000
#define DIM 64
#define NCHUNK 98          // 98*512 = 50176 >= 50000 ; co-resident for lookback scan
#define NCONV (N_NODES * DIM / 8)   // 400000 conv work-items (8 floats each)
#define XS_STRIDE 72       // halves; 144B rows -> ldmatrix conflict-free

// ---- device scratch (no allocations allowed; static zero-init) ----
__device__ int   g_counts[N_NODES];      // invariant: zero at entry of every replay
__device__ int   g_offsets[N_NODES + 1];
__device__ int   g_cursor[N_NODES];
__device__ int   g_csum[NCHUNK];
__device__ volatile int g_cflag[NCHUNK]; // invariant: zero at entry (reset by k_scatter)
__device__ int   g_srcidx[N_EDGES];
__device__ __align__(16) __half g_hha[N_NODES * DIM];  // fp16 activations (ping)
__device__ __align__(16) __half g_hhb[N_NODES * DIM];  // fp16 activations (pong)

// ---- mma helpers ----
__device__ __forceinline__ void ldsm_x4(unsigned* r, unsigned addr) {
    asm volatile("ldmatrix.sync.aligned.m8n8.x4.shared.b16 {%0,%1,%2,%3}, [%4];"
        : "=r"(r[0]), "=r"(r[1]), "=r"(r[2]), "=r"(r[3]) : "r"(addr));
}
__device__ __forceinline__ void ldsm_x4_t(unsigned* r, unsigned addr) {
    asm volatile("ldmatrix.sync.aligned.m8n8.x4.trans.shared.b16 {%0,%1,%2,%3}, [%4];"
        : "=r"(r[0]), "=r"(r[1]), "=r"(r[2]), "=r"(r[3]) : "r"(addr));
}
__device__ __forceinline__ void mma16816(float* d, const unsigned* a,
                                         unsigned b0, unsigned b1) {
    asm volatile(
        "mma.sync.aligned.m16n8k16.row.col.f32.f16.f16.f32 "
        "{%0,%1,%2,%3}, {%4,%5,%6,%7}, {%8,%9}, {%0,%1,%2,%3};"
        : "+f"(d[0]), "+f"(d[1]), "+f"(d[2]), "+f"(d[3])
        : "r"(a[0]), "r"(a[1]), "r"(a[2]), "r"(a[3]), "r"(b0), "r"(b1));
}

// ---------------- CSR build ----------------

// fused: degree count (1 edge/thread, max TLP) + fp16 conversion of n_feat
__global__ void k_count_conv(const int* __restrict__ dst,
                             const float* __restrict__ f) {
    int i = blockIdx.x * blockDim.x + threadIdx.x;
    if (i < N_EDGES)
        atomicAdd(&g_counts[__ldg(dst + i)], 1);
    if (i < NCONV) {
        float4 v0 = __ldg((const float4*)f + i * 2);
        float4 v1 = __ldg((const float4*)f + i * 2 + 1);
        __half2 hs[4];
        hs[0] = __floats2half2_rn(v0.x, v0.y);
        hs[1] = __floats2half2_rn(v0.z, v0.w);
        hs[2] = __floats2half2_rn(v1.x, v1.y);
        hs[3] = __floats2half2_rn(v1.z, v1.w);
        *(uint4*)((__half2*)g_hha + i * 4) = *(uint4*)hs;
    }
}

// single-kernel scan via decoupled lookback (all 98 blocks co-resident)
__global__ void __launch_bounds__(512) k_scan() {
    __shared__ int warp_sums[16];
    __shared__ int prefix_s;
    const int t = threadIdx.x, lane = t & 31, wid = t >> 5;
    const int c = blockIdx.x;
    const int i = c * 512 + t;

    int v = (i < N_NODES) ? g_counts[i] : 0;
    int s = v;
    #pragma unroll
    for (int d = 1; d < 32; d <<= 1) {
        int y = __shfl_up_sync(0xffffffffu, s, d);
        if (lane >= d) s += y;
    }
    if (lane == 31) warp_sums[wid] = s;
    __syncthreads();
    if (wid == 0 && lane < 16) {
        int ws = warp_sums[lane];
        #pragma unroll
        for (int d = 1; d < 16; d <<= 1) {
            int y = __shfl_up_sync(0xffffu, ws, d);
            if (lane >= d) ws += y;
        }
        warp_sums[lane] = ws;
    }
    __syncthreads();
    int excl = s - v + (wid > 0 ? warp_sums[wid - 1] : 0);

    if (t == 511) {
        g_csum[c] = excl + v;
        __threadfence();
        g_cflag[c] = 1;
    }
    if (t < 32) {
        int acc = 0;
        for (int j = lane; j < c; j += 32) {
            while (g_cflag[j] == 0) { }
            acc += *(volatile int*)&g_csum[j];
        }
        #pragma unroll
        for (int d = 16; d > 0; d >>= 1) acc += __shfl_down_sync(0xffffffffu, acc, d);
        if (lane == 0) prefix_s = acc;
    }
    __syncthreads();
    int prefix = prefix_s;

    if (i < N_NODES) {
        int o = excl + prefix;
        g_offsets[i] = o;
        g_cursor[i]  = o;
        g_counts[i]  = 0;
    }
    if (c == NCHUNK - 1 && t == 511)
        g_offsets[N_NODES] = prefix + excl + v;
}

// 2 edges per thread (int2), 400K threads for latency hiding
__global__ void k_scatter(const int* __restrict__ src, const int* __restrict__ dst) {
    int i = blockIdx.x * blockDim.x + threadIdx.x;
    if (i < NCHUNK) g_cflag[i] = 0;              // flag reset (invariant)
    if (i < N_EDGES / 2) {
        int2 s2 = __ldg((const int2*)src + i);
        int2 d2 = __ldg((const int2*)dst + i);
        g_srcidx[atomicAdd(&g_cursor[d2.x], 1)] = s2.x;
        g_srcidx[atomicAdd(&g_cursor[d2.y], 1)] = s2.y;
    }
}

// ---------------- fused layer: agg (fp16 segment-max) + mma.sync GEMM ----------
// 512 threads, tile = 64 nodes. All activations fp16 (self term included —
// X is rounded to fp16 before the tensor-core GEMM anyway).
// Layers 0/1 write ONLY the fp16 shadow; layer 2 writes ONLY fp32 d_out.
__global__ void __launch_bounds__(512, 3) k_layer(
        const __half* __restrict__ hh,        // fp16 activations (gathers + self)
        const float* __restrict__ W,
        const float* __restrict__ bias,
        const float* __restrict__ eps, int layer,
        float* __restrict__ out,              // fp32 out (final layer only)
        __half* __restrict__ hh_out,          // fp16 out (layers 0/1)
        int activate, int write_hh) {
    __shared__ __half Wsh[64 * XS_STRIDE];    // [k][j] fp16
    __shared__ __half Xsh[64 * XS_STRIDE];    // [node][k] fp16

    int t = threadIdx.x;              // 0..511
    int base = blockIdx.x * 64;

    // convert W to fp16 smem (each thread: 2 float4 = 8 values)
    #pragma unroll
    for (int p = 0; p < 2; p++) {
        int i4 = t + p * 512;         // 0..1023 float4s
        float4 w = __ldg((const float4*)W + i4);
        int kk = i4 >> 4;             // 16 float4 per 64-col row
        int j  = (i4 & 15) * 4;
        __half2* d2 = (__half2*)&Wsh[kk * XS_STRIDE + j];
        d2[0] = __floats2half2_rn(w.x, w.y);
        d2[1] = __floats2half2_rn(w.z, w.w);
    }

    float ep = 1.0f + __ldg(eps + layer);
    int warp = t >> 5, lane = t & 31;

    // ---- phase 1: fp16 aggregation, batch-16 gathers (R15 loop) ----
    #pragma unroll
    for (int q = 0; q < 4; q++) {
        int nl = warp * 4 + q;
        int n = base + nl;
        if (n < N_NODES) {
            int beg = g_offsets[n];
            int end = g_offsets[n + 1];
            __half2 m = __float2half2_rn(-CUDART_INF_F);
            int i = beg;
            for (; i + 16 <= end; i += 16) {
                int sx[16];
                #pragma unroll
                for (int u = 0; u < 16; u++) sx[u] = __ldg(&g_srcidx[i + u]);
                __half2 a[16];
                #pragma unroll
                for (int u = 0; u < 16; u++)
                    a[u] = __ldg((const __half2*)(hh + (size_t)sx[u] * DIM) + lane);
                #pragma unroll
                for (int u = 0; u < 16; u++) m = __hmax2(m, a[u]);
            }
            for (; i + 8 <= end; i += 8) {
                int sx[8];
                #pragma unroll
                for (int u = 0; u < 8; u++) sx[u] = __ldg(&g_srcidx[i + u]);
                __half2 a[8];
                #pragma unroll
                for (int u = 0; u < 8; u++)
                    a[u] = __ldg((const __half2*)(hh + (size_t)sx[u] * DIM) + lane);
                #pragma unroll
                for (int u = 0; u < 8; u++) m = __hmax2(m, a[u]);
            }
            for (; i < end; ++i) {
                int s = __ldg(&g_srcidx[i]);
                __half2 a = __ldg((const __half2*)(hh + (size_t)s * DIM) + lane);
                m = __hmax2(m, a);
            }
            float2 mf = __half22float2(m);
            if (beg == end) { mf.x = 0.0f; mf.y = 0.0f; }   // DGL zero-fill
            float2 hs = __half22float2(
                __ldg((const __half2*)(hh + (size_t)n * DIM) + lane));
            float xx = fmaf(ep, hs.x, mf.x);
            float xy = fmaf(ep, hs.y, mf.y);
            *(__half2*)&Xsh[nl * XS_STRIDE + lane * 2] = __floats2half2_rn(xx, xy);
        }
    }
    __syncthreads();                  // Wsh + Xsh ready

    // ---- phase 2: tensor-core GEMM out[64x64] = Xsh @ Wsh ----
    int warpM = warp >> 2;            // 0..3 : node rows warpM*16..+15
    int warpN = warp & 3;             // 0..3 : cols warpN*16..+15
    int lr = lane & 15, lc = lane >> 4;

    unsigned xs_u32 = (unsigned)__cvta_generic_to_shared(Xsh);
    unsigned ws_u32 = (unsigned)__cvta_generic_to_shared(Wsh);

    unsigned a_addr = xs_u32 + (((warpM * 16 + lr) * XS_STRIDE) + lc * 8) * 2;
    unsigned b_addr = ws_u32 + ((lr * XS_STRIDE) + warpN * 16 + lc * 8) * 2;

    float acc0[4] = {0.f, 0.f, 0.f, 0.f};
    float acc1[4] = {0.f, 0.f, 0.f, 0.f};

    #pragma unroll
    for (int kk = 0; kk < 4; kk++) {
        unsigned a[4], b[4];
        ldsm_x4(a, a_addr + kk * 32);                         // +16 halves
        ldsm_x4_t(b, b_addr + kk * 16 * XS_STRIDE * 2);       // +16 k-rows
        mma16816(acc0, a, b[0], b[1]);
        mma16816(acc1, a, b[2], b[3]);
    }

    // ---- epilogue: bias + leaky; fp16 store (layers 0/1) OR fp32 (layer 2) ----
    int r  = lane >> 2;               // row within m16 (and +8)
    int cq = lane & 3;                // col quad
    int n0 = base + warpM * 16 + r;
    int n1 = n0 + 8;

    #pragma unroll
    for (int nn = 0; nn < 2; nn++) {
        float* acc = nn ? acc1 : acc0;
        int col = warpN * 16 + nn * 8 + cq * 2;
        float2 bb = *(const float2*)(bias + col);
        float v0 = acc[0] + bb.x, v1 = acc[1] + bb.y;   // row r
        float v2 = acc[2] + bb.x, v3 = acc[3] + bb.y;   // row r+8
        if (activate) {
            v0 = v0 >= 0.f ? v0 : 0.01f * v0;
            v1 = v1 >= 0.f ? v1 : 0.01f * v1;
            v2 = v2 >= 0.f ? v2 : 0.01f * v2;
            v3 = v3 >= 0.f ? v3 : 0.01f * v3;
        }
        if (write_hh) {
            if (n0 < N_NODES)
                *(__half2*)(hh_out + (size_t)n0 * DIM + col) = __floats2half2_rn(v0, v1);
            if (n1 < N_NODES)
                *(__half2*)(hh_out + (size_t)n1 * DIM + col) = __floats2half2_rn(v2, v3);
        } else {
            if (n0 < N_NODES)
                *(float2*)&out[(size_t)n0 * DIM + col] = make_float2(v0, v1);
            if (n1 < N_NODES)
                *(float2*)&out[(size_t)n1 * DIM + col] = make_float2(v2, v3);
        }
    }
}

// ---------------- launch ----------------
extern "C" void kernel_launch(void* const* d_in, const int* in_sizes, int n_in,
                              void* d_out, int out_size) {
    const float* n_feat = (const float*)d_in[0];
    const float* W0 = (const float*)d_in[1];
    const float* b0 = (const float*)d_in[2];
    const float* W1 = (const float*)d_in[3];
    const float* b1 = (const float*)d_in[4];
    const float* W2 = (const float*)d_in[5];
    const float* b2 = (const float*)d_in[6];
    const float* eps = (const float*)d_in[7];
    const int*   src = (const int*)d_in[8];
    const int*   dst = (const int*)d_in[9];
    float* out = (float*)d_out;

    __half *hha_ptr, *hhb_ptr;
    cudaGetSymbolAddress((void**)&hha_ptr, g_hha);
    cudaGetSymbolAddress((void**)&hhb_ptr, g_hhb);

    // CSR build + fp16 conversion (3 launches)
    k_count_conv<<<(N_EDGES + 255) / 256, 256>>>(dst, n_feat);
    k_scan<<<NCHUNK, 512>>>();
    k_scatter<<<(N_EDGES / 2 + 255) / 256, 256>>>(src, dst);

    const int layer_blocks = (N_NODES + 63) / 64;   // 782

    // layer 0: read hha, write hhb (fp16 only)
    k_layer<<<layer_blocks, 512>>>(hha_ptr, W0, b0, eps, 0, out, hhb_ptr, 1, 1);
    // layer 1: read hhb, write hha (fp16 only)
    k_layer<<<layer_blocks, 512>>>(hhb_ptr, W1, b1, eps, 1, out, hha_ptr, 1, 1);
    // layer 2: read hha, write fp32 d_out
    k_layer<<<layer_blocks, 512>>>(hha_ptr, W2, b2, eps, 2, out, hhb_ptr, 0, 0);
}